// round 6
// baseline (speedup 1.0000x reference)
#include <cuda_runtime.h>
#include <math.h>
#include <cstdint>

#define S_TOK 4096
#define NH    12
#define HD    64
#define NROWS (S_TOK*NH)
#define QTILE 128
#define KTILE 32
#define NTILES (S_TOK/KTILE)

// SMEM geometry (bytes)
#define KROWB 320              // 32 float2 (256B) + 64B pad -> perfect LDS.64 banks
#define VROWB 576              // 64 float2 (512B) + 64B pad
#define K_TILE_B (32*KROWB)    // 10240
#define V_TILE_B (16*VROWB)    // 9216
#define K_OFF   0
#define V_OFF   (2*K_TILE_B)
#define QP_OFF  (V_OFF + 2*V_TILE_B)    // 38912
#define QSTR 76                          // floats per QP row
#define SMEM_BYTES (QP_OFF + 128*QSTR*4) // 77824

// ---------------- scratch ---------------------------------------------------
// g_k: per (h,tile): [c][n] float2, c=tt*4+j -> (K[n][tt*8+j], K[n][tt*8+j+4])
// g_v: per (h,tile): [cp][n] float2, cp=tk*4+j -> (V[tk*8+j][n], V[tk*8+j+4][n])
__device__ float g_k[(size_t)NH*S_TOK*HD];
__device__ float g_v[(size_t)NH*S_TOK*HD];
__device__ float g_P[4][16];
__device__ float g_PT[4][16];
__device__ float g_Pinv[4][16];
__device__ float g_cos[32][8];
__device__ float g_sin[32][8];

__device__ __forceinline__ float tf32r(float x) {
    float r; asm("cvt.rna.tf32.f32 %0,%1;" : "=f"(r) : "f"(x)); return r;
}
__device__ __forceinline__ float ex2(float x) {
    float y; asm("ex2.approx.ftz.f32 %0,%1;" : "=f"(y) : "f"(x)); return y;
}
__device__ __forceinline__ uint32_t smem_u32(const void* p) {
    uint32_t a;
    asm("{ .reg .u64 t; cvta.to.shared.u64 t, %1; cvt.u32.u64 %0, t; }" : "=r"(a) : "l"(p));
    return a;
}
__device__ __forceinline__ void cp16(uint32_t dst, const void* src) {
    asm volatile("cp.async.cg.shared.global [%0], [%1], 16;" :: "r"(dst), "l"(src) : "memory");
}
#define CP_COMMIT() asm volatile("cp.async.commit_group;" ::: "memory")
#define CP_WAIT0()  asm volatile("cp.async.wait_group 0;" ::: "memory")

__device__ __forceinline__ void mma_tf32(float* d, const uint32_t* a, float b0f, float b1f) {
    uint32_t b0 = __float_as_uint(b0f), b1 = __float_as_uint(b1f);
    asm volatile("mma.sync.aligned.m16n8k8.row.col.f32.tf32.tf32.f32 "
        "{%0,%1,%2,%3}, {%4,%5,%6,%7}, {%8,%9}, {%0,%1,%2,%3};"
        : "+f"(d[0]), "+f"(d[1]), "+f"(d[2]), "+f"(d[3])
        : "r"(a[0]), "r"(a[1]), "r"(a[2]), "r"(a[3]), "r"(b0), "r"(b1));
}

__device__ __forceinline__ void mm4(const float* A, const float* B, float* Cm) {
#pragma unroll
    for (int i = 0; i < 4; i++)
#pragma unroll
        for (int j = 0; j < 4; j++) {
            float s = 0.f;
#pragma unroll
            for (int kk = 0; kk < 4; kk++) s += A[i*4+kk] * B[kk*4+j];
            Cm[i*4+j] = s;
        }
}

// ---------------------------------------------------------------------------
__global__ void prep_kernel(const float* __restrict__ vm, const float* __restrict__ Ks) {
    int t = threadIdx.x;
    if (t < 32) {
        float L = log2f(100.0f);
#pragma unroll
        for (int i = 0; i < 8; i++) {
            float f = exp2f(-L * (float)i / 8.0f);
            float sv, cv; sincosf((float)t * f, &sv, &cv);
            g_cos[t][i] = cv; g_sin[t][i] = sv;
        }
    }
    if (t < 4) {
        int c = t;
        const float* V  = vm + c*16;
        const float* Kc = Ks + c*9;
        float a = Kc[0] * (1.0f/512.0f);
        float b = Kc[4] * (1.0f/512.0f);
        float u = Kc[2] * (1.0f/512.0f) - 0.5f;
        float w = Kc[5] * (1.0f/512.0f) - 0.5f;
        float K4[16] = {a,0,u,0, 0,b,w,0, 0,0,1,0, 0,0,0,1};
        float Vl[16];
#pragma unroll
        for (int i = 0; i < 16; i++) Vl[i] = V[i];
        float P[16];
        mm4(K4, Vl, P);
#pragma unroll
        for (int i = 0; i < 4; i++)
#pragma unroll
            for (int jj = 0; jj < 4; jj++) { g_P[c][i*4+jj] = P[i*4+jj]; g_PT[c][i*4+jj] = P[jj*4+i]; }
        float Sm[16];
#pragma unroll
        for (int i = 0; i < 3; i++)
#pragma unroll
            for (int jj = 0; jj < 3; jj++) Sm[i*4+jj] = Vl[jj*4+i];
#pragma unroll
        for (int i = 0; i < 3; i++)
            Sm[i*4+3] = -(Sm[i*4+0]*Vl[3] + Sm[i*4+1]*Vl[7] + Sm[i*4+2]*Vl[11]);
        Sm[12]=0.f; Sm[13]=0.f; Sm[14]=0.f; Sm[15]=1.f;
        float Ki[16] = {1.0f/a,0,-u/a,0, 0,1.0f/b,-w/b,0, 0,0,1,0, 0,0,0,1};
        float Pi[16];
        mm4(Sm, Ki, Pi);
#pragma unroll
        for (int i = 0; i < 16; i++) g_Pinv[c][i] = Pi[i];
    }
}

// ---------------------------------------------------------------------------
__device__ __forceinline__ void transform_row_regs(
    const float* __restrict__ in, float* __restrict__ y,
    const float* M, int px, int py)
{
    float x[64];
    const float4* in4 = (const float4*)in;
#pragma unroll
    for (int i = 0; i < 16; i++) {
        float4 tv = in4[i];
        x[4*i+0]=tv.x; x[4*i+1]=tv.y; x[4*i+2]=tv.z; x[4*i+3]=tv.w;
    }
#pragma unroll
    for (int g = 0; g < 8; g++)
#pragma unroll
        for (int i = 0; i < 4; i++)
            y[g*4+i] = M[i*4+0]*x[g*4+0] + M[i*4+1]*x[g*4+1]
                     + M[i*4+2]*x[g*4+2] + M[i*4+3]*x[g*4+3];
#pragma unroll
    for (int i = 0; i < 8; i++) {
        float c1 = g_cos[px][i], s1 = g_sin[px][i];
        y[32+i] =  c1*x[32+i] + s1*x[40+i];
        y[40+i] = -s1*x[32+i] + c1*x[40+i];
        float c2 = g_cos[py][i], s2 = g_sin[py][i];
        y[48+i] =  c2*x[48+i] + s2*x[56+i];
        y[56+i] = -s2*x[48+i] + c2*x[56+i];
    }
#pragma unroll
    for (int i = 0; i < 64; i++) y[i] = tf32r(y[i]);
}

// thread r = h*4096 + s (warp = one 32-token tile)
__global__ void transform_kv_kernel(const float* __restrict__ k, const float* __restrict__ v) {
    int r = blockIdx.x * blockDim.x + threadIdx.x;
    if (r >= NROWS) return;
    int h = r >> 12;
    int s = r & 4095;
    int cam = s >> 10;
    int px = s & 31;
    int py = (s >> 5) & 31;
    float M[16];
#pragma unroll
    for (int i = 0; i < 16; i++) M[i] = g_Pinv[cam][i];
    size_t ib = ((size_t)s * NH + h) * HD;

    float yk[64], yv[64];
    transform_row_regs(k + ib, yk, M, px, py);
    transform_row_regs(v + ib, yv, M, px, py);

    int t = s >> 5, n = s & 31;

    // K: paired over dims, [c][n] float2, coalesced across warp
    float2* kt = (float2*)g_k + ((size_t)h*128 + t) * 1024;
#pragma unroll
    for (int cc = 0; cc < 32; cc++) {
        int dlo = (cc >> 2)*8 + (cc & 3);
        kt[cc*32 + n] = make_float2(yk[dlo], yk[dlo+4]);
    }

    // V: paired over keys, [cp][n2] float2; this token writes one scalar lane of each pair
    float* vt = g_v + ((size_t)h*128 + t) * 2048;
    int l3 = n & 7;
    int cpr = (n >> 3)*4 + (l3 & 3);
    int elem = l3 >> 2;
    float* vrow = vt + cpr*128 + elem;
#pragma unroll
    for (int n2 = 0; n2 < 64; n2++) vrow[n2*2] = yv[n2];
}

// ---------------------------------------------------------------------------
// Flash attention via mma.sync.m16n8k8.tf32, cp.async double buffering,
// pre-paired B-fragment layouts (1 LDS.64 per fragment, conflict-free).
// ---------------------------------------------------------------------------
__global__ void __launch_bounds__(QTILE)
attn_kernel(const float* __restrict__ q, float* __restrict__ out) {
    extern __shared__ char smraw[];
    const uint32_t sb = smem_u32(smraw);
    float* QP = (float*)(smraw + QP_OFF);

    const int tid  = threadIdx.x;
    const int w    = tid >> 5, lane = tid & 31;
    const int g    = lane >> 2, j = lane & 3;
    const int h    = blockIdx.y;
    const int s    = blockIdx.x * QTILE + tid;
    const int cam  = s >> 10, px = s & 31, py = (s >> 5) & 31;

    const float* kg = g_k + (size_t)h * S_TOK * HD;   // 128 tiles * 2048 floats
    const float* vg = g_v + (size_t)h * S_TOK * HD;

    // ---- prefetch tile 0 ----
#pragma unroll
    for (int i = 0; i < 4; i++) {
        int idx = tid + i*128;  // 0..511 chunks of 16B
        cp16(sb + K_OFF + (uint32_t)(idx >> 4)*KROWB + (uint32_t)(idx & 15)*16, kg + idx*4);
        cp16(sb + V_OFF + (uint32_t)(idx >> 5)*VROWB + (uint32_t)(idx & 31)*16, vg + idx*4);
    }
    CP_COMMIT();

    // ---- Q transform (PT proj + fwd RoPE), fold scale*log2e, -> SMEM ----
    {
        float x[64];
        const float4* qr = (const float4*)(q + (size_t)s * (NH*HD) + (size_t)h * HD);
#pragma unroll
        for (int i = 0; i < 16; i++) {
            float4 tv = qr[i];
            x[4*i+0]=tv.x; x[4*i+1]=tv.y; x[4*i+2]=tv.z; x[4*i+3]=tv.w;
        }
        float y[64];
        const float* M = g_PT[cam];
#pragma unroll
        for (int gg = 0; gg < 8; gg++)
#pragma unroll
            for (int i = 0; i < 4; i++)
                y[gg*4+i] = M[i*4+0]*x[gg*4+0] + M[i*4+1]*x[gg*4+1]
                          + M[i*4+2]*x[gg*4+2] + M[i*4+3]*x[gg*4+3];
#pragma unroll
        for (int i = 0; i < 8; i++) {
            float c1 = g_cos[px][i], s1 = g_sin[px][i];
            y[32+i] =  c1*x[32+i] + s1*x[40+i];
            y[40+i] = -s1*x[32+i] + c1*x[40+i];
            float c2 = g_cos[py][i], s2 = g_sin[py][i];
            y[48+i] =  c2*x[48+i] + s2*x[56+i];
            y[56+i] = -s2*x[48+i] + c2*x[56+i];
        }
        const float SC = 0.18033688011112042f;  // (1/8)*log2(e)
        float4* dst = (float4*)&QP[(size_t)tid*QSTR];
#pragma unroll
        for (int i = 0; i < 16; i++)
            dst[i] = make_float4(tf32r(y[4*i+0]*SC), tf32r(y[4*i+1]*SC),
                                 tf32r(y[4*i+2]*SC), tf32r(y[4*i+3]*SC));
    }
    __syncthreads();

    // ---- Q A-fragments ----
    uint32_t qa[2][8][4];
#pragma unroll
    for (int m = 0; m < 2; m++)
#pragma unroll
        for (int t = 0; t < 8; t++) {
            int r0 = w*32 + m*16 + g, r1 = r0 + 8;
            qa[m][t][0] = __float_as_uint(QP[r0*QSTR + t*8+j]);
            qa[m][t][1] = __float_as_uint(QP[r1*QSTR + t*8+j]);
            qa[m][t][2] = __float_as_uint(QP[r0*QSTR + t*8+4+j]);
            qa[m][t][3] = __float_as_uint(QP[r1*QSTR + t*8+4+j]);
        }

    float o[2][8][4];
#pragma unroll
    for (int m = 0; m < 2; m++)
#pragma unroll
        for (int nb = 0; nb < 8; nb++)
#pragma unroll
            for (int e = 0; e < 4; e++) o[m][nb][e] = 0.f;
    float mrow[4] = {-1e30f, -1e30f, -1e30f, -1e30f};
    float lsum[4] = {0.f, 0.f, 0.f, 0.f};

#pragma unroll 1
    for (int t = 0; t < NTILES; t++) {
        CP_WAIT0();
        __syncthreads();

        const char* Kb = smraw + K_OFF + (t & 1) * K_TILE_B;
        const char* Vb = smraw + V_OFF + (t & 1) * V_TILE_B;

        // ---- prefetch next tile ----
        if (t + 1 < NTILES) {
            const float* ksrc = kg + (size_t)(t+1) * 2048;
            const float* vsrc = vg + (size_t)(t+1) * 2048;
            uint32_t kb = sb + K_OFF + (uint32_t)((t+1) & 1) * K_TILE_B;
            uint32_t vb = sb + V_OFF + (uint32_t)((t+1) & 1) * V_TILE_B;
#pragma unroll
            for (int i = 0; i < 4; i++) {
                int idx = tid + i*128;
                cp16(kb + (uint32_t)(idx >> 4)*KROWB + (uint32_t)(idx & 15)*16, ksrc + idx*4);
                cp16(vb + (uint32_t)(idx >> 5)*VROWB + (uint32_t)(idx & 31)*16, vsrc + idx*4);
            }
            CP_COMMIT();
        }

        // ---- GEMM1: S(128x32) = Q @ K^T  (paired B: 1 LDS.64/frag) ----
        float sc[2][4][4];
#pragma unroll
        for (int m = 0; m < 2; m++)
#pragma unroll
            for (int nb = 0; nb < 4; nb++)
#pragma unroll
                for (int e = 0; e < 4; e++) sc[m][nb][e] = 0.f;
#pragma unroll
        for (int nb = 0; nb < 4; nb++)
#pragma unroll
            for (int tt = 0; tt < 8; tt++) {
                float2 b = *(const float2*)(Kb + (tt*4 + j)*KROWB + (nb*8 + g)*8);
                mma_tf32(sc[0][nb], qa[0][tt], b.x, b.y);
                mma_tf32(sc[1][nb], qa[1][tt], b.x, b.y);
            }

        // ---- online softmax (log2 domain) ----
        float rs[4];
#pragma unroll
        for (int m = 0; m < 2; m++)
#pragma unroll
            for (int hi = 0; hi < 2; hi++) {
                int rc = m*2 + hi;
                float mt = -1e30f;
#pragma unroll
                for (int nb = 0; nb < 4; nb++) {
                    mt = fmaxf(mt, sc[m][nb][hi*2]);
                    mt = fmaxf(mt, sc[m][nb][hi*2+1]);
                }
                mt = fmaxf(mt, __shfl_xor_sync(0xffffffffu, mt, 1));
                mt = fmaxf(mt, __shfl_xor_sync(0xffffffffu, mt, 2));
                float mn = fmaxf(mrow[rc], mt);
                rs[rc] = ex2(mrow[rc] - mn);
                mrow[rc] = mn;
                float ps = 0.f;
#pragma unroll
                for (int nb = 0; nb < 4; nb++) {
                    float p0 = ex2(sc[m][nb][hi*2]   - mn);
                    float p1 = ex2(sc[m][nb][hi*2+1] - mn);
                    sc[m][nb][hi*2] = p0; sc[m][nb][hi*2+1] = p1;
                    ps += p0 + p1;
                }
                ps += __shfl_xor_sync(0xffffffffu, ps, 1);
                ps += __shfl_xor_sync(0xffffffffu, ps, 2);
                lsum[rc] = lsum[rc]*rs[rc] + ps;
            }

        // ---- store P (tf32) into own warp's QP rows ----
#pragma unroll
        for (int m = 0; m < 2; m++) {
            int r0 = w*32 + m*16 + g, r1 = r0 + 8;
#pragma unroll
            for (int nb = 0; nb < 4; nb++) {
                *(float2*)&QP[r0*QSTR + nb*8 + 2*j] =
                    make_float2(tf32r(sc[m][nb][0]), tf32r(sc[m][nb][1]));
                *(float2*)&QP[r1*QSTR + nb*8 + 2*j] =
                    make_float2(tf32r(sc[m][nb][2]), tf32r(sc[m][nb][3]));
            }
        }
        __syncwarp();

        // ---- rescale O (skipped when no row max moved) ----
        bool allone = (rs[0]==1.f) & (rs[1]==1.f) & (rs[2]==1.f) & (rs[3]==1.f);
        if (!__all_sync(0xffffffffu, allone)) {
#pragma unroll
            for (int m = 0; m < 2; m++)
#pragma unroll
                for (int nb = 0; nb < 8; nb++) {
                    o[m][nb][0] *= rs[m*2];   o[m][nb][1] *= rs[m*2];
                    o[m][nb][2] *= rs[m*2+1]; o[m][nb][3] *= rs[m*2+1];
                }
        }

        // ---- GEMM2: O += P @ V  (paired V: 1 LDS.64/frag) ----
#pragma unroll
        for (int tk = 0; tk < 4; tk++) {
            uint32_t pa0[4], pa1[4];
            int r0 = w*32 + g, r1 = r0 + 8;
            pa0[0] = __float_as_uint(QP[ r0     *QSTR + tk*8 + j]);
            pa0[1] = __float_as_uint(QP[ r1     *QSTR + tk*8 + j]);
            pa0[2] = __float_as_uint(QP[ r0     *QSTR + tk*8 + 4 + j]);
            pa0[3] = __float_as_uint(QP[ r1     *QSTR + tk*8 + 4 + j]);
            pa1[0] = __float_as_uint(QP[(r0+16)*QSTR + tk*8 + j]);
            pa1[1] = __float_as_uint(QP[(r1+16)*QSTR + tk*8 + j]);
            pa1[2] = __float_as_uint(QP[(r0+16)*QSTR + tk*8 + 4 + j]);
            pa1[3] = __float_as_uint(QP[(r1+16)*QSTR + tk*8 + 4 + j]);
#pragma unroll
            for (int nb = 0; nb < 8; nb++) {
                float2 b = *(const float2*)(Vb + (tk*4 + j)*VROWB + (nb*8 + g)*8);
                mma_tf32(o[0][nb], pa0, b.x, b.y);
                mma_tf32(o[1][nb], pa1, b.x, b.y);
            }
        }
    }

    // ---- normalize, exchange O through SMEM, epilogue ----
    __syncthreads();
    float inv[4];
#pragma unroll
    for (int rc = 0; rc < 4; rc++) inv[rc] = 1.0f / lsum[rc];
#pragma unroll
    for (int m = 0; m < 2; m++) {
        int r0 = w*32 + m*16 + g, r1 = r0 + 8;
#pragma unroll
        for (int nb = 0; nb < 8; nb++) {
            *(float2*)&QP[r0*QSTR + nb*8 + 2*j] =
                make_float2(o[m][nb][0]*inv[m*2],   o[m][nb][1]*inv[m*2]);
            *(float2*)&QP[r1*QSTR + nb*8 + 2*j] =
                make_float2(o[m][nb][2]*inv[m*2+1], o[m][nb][3]*inv[m*2+1]);
        }
    }
    __syncthreads();

    {
        float acc[64];
#pragma unroll
        for (int i = 0; i < 16; i++) {
            float4 tv = *(const float4*)&QP[(size_t)tid*QSTR + i*4];
            acc[4*i+0]=tv.x; acc[4*i+1]=tv.y; acc[4*i+2]=tv.z; acc[4*i+3]=tv.w;
        }
        float y[64];
        const float* M = g_P[cam];
#pragma unroll
        for (int gg = 0; gg < 8; gg++)
#pragma unroll
            for (int i = 0; i < 4; i++)
                y[gg*4+i] = M[i*4+0]*acc[gg*4+0] + M[i*4+1]*acc[gg*4+1]
                          + M[i*4+2]*acc[gg*4+2] + M[i*4+3]*acc[gg*4+3];
#pragma unroll
        for (int i = 0; i < 8; i++) {
            float c1 = g_cos[px][i], s1 = g_sin[px][i];
            y[32+i] = c1*acc[32+i] - s1*acc[40+i];
            y[40+i] = s1*acc[32+i] + c1*acc[40+i];
            float c2 = g_cos[py][i], s2 = g_sin[py][i];
            y[48+i] = c2*acc[48+i] - s2*acc[56+i];
            y[56+i] = s2*acc[48+i] + c2*acc[56+i];
        }
        float4* o4 = (float4*)(out + (size_t)s * (NH*HD) + (size_t)h * HD);
#pragma unroll
        for (int i = 0; i < 16; i++)
            o4[i] = make_float4(y[4*i+0], y[4*i+1], y[4*i+2], y[4*i+3]);
    }
}

// ---------------------------------------------------------------------------
extern "C" void kernel_launch(void* const* d_in, const int* in_sizes, int n_in,
                              void* d_out, int out_size) {
    const float* q  = (const float*)d_in[0];
    const float* k  = (const float*)d_in[1];
    const float* v  = (const float*)d_in[2];
    const float* vm = (const float*)d_in[3];
    const float* Ks = (const float*)d_in[4];
    float* out = (float*)d_out;

    cudaFuncSetAttribute(attn_kernel, cudaFuncAttributeMaxDynamicSharedMemorySize, SMEM_BYTES);

    prep_kernel<<<1, 32>>>(vm, Ks);
    transform_kv_kernel<<<(NROWS + 255) / 256, 256>>>(k, v);
    attn_kernel<<<dim3(S_TOK / QTILE, NH), QTILE, SMEM_BYTES>>>(q, out);
}

// round 7
// speedup vs baseline: 1.1454x; 1.1454x over previous
#include <cuda_runtime.h>
#include <math.h>
#include <cstdint>

#define S_TOK 4096
#define NH    12
#define HD    64
#define NROWS (S_TOK*NH)
#define QTILE 128
#define KTILE 32
#define NTILES (S_TOK/KTILE)

// SMEM geometry (floats)
#define KSTR 68
#define VSTR 72
#define QSTR 76
#define K_OFF   0
#define K_BUF_B (32*KSTR*4)
#define V_OFF   (2*K_BUF_B)
#define V_BUF_B (32*VSTR*4)
#define QP_OFF  (V_OFF + 2*V_BUF_B)
#define SMEM_BYTES (QP_OFF + 128*QSTR*4)

// ---------------- scratch ---------------------------------------------------
__device__ float g_k[(size_t)NH*S_TOK*HD];   // [h][s][d], tf32-rounded
__device__ float g_v[(size_t)NH*S_TOK*HD];   // [h][s][d], tf32-rounded
__device__ float g_P[4][16];
__device__ float g_PT[4][16];
__device__ float g_Pinv[4][16];
__device__ float g_cos[32][8];
__device__ float g_sin[32][8];

__device__ __forceinline__ float tf32r(float x) {
    float r; asm("cvt.rna.tf32.f32 %0,%1;" : "=f"(r) : "f"(x)); return r;
}
__device__ __forceinline__ float ex2(float x) {
    float y; asm("ex2.approx.ftz.f32 %0,%1;" : "=f"(y) : "f"(x)); return y;
}
__device__ __forceinline__ uint32_t smem_u32(const void* p) {
    uint32_t a;
    asm("{ .reg .u64 t; cvta.to.shared.u64 t, %1; cvt.u32.u64 %0, t; }" : "=r"(a) : "l"(p));
    return a;
}
__device__ __forceinline__ void cp16(uint32_t dst, const void* src) {
    asm volatile("cp.async.cg.shared.global [%0], [%1], 16;" :: "r"(dst), "l"(src) : "memory");
}
#define CP_COMMIT() asm volatile("cp.async.commit_group;" ::: "memory")
#define CP_WAIT0()  asm volatile("cp.async.wait_group 0;" ::: "memory")

__device__ __forceinline__ void mma_tf32(float* d, const uint32_t* a, float b0f, float b1f) {
    uint32_t b0 = __float_as_uint(b0f), b1 = __float_as_uint(b1f);
    asm volatile("mma.sync.aligned.m16n8k8.row.col.f32.tf32.tf32.f32 "
        "{%0,%1,%2,%3}, {%4,%5,%6,%7}, {%8,%9}, {%0,%1,%2,%3};"
        : "+f"(d[0]), "+f"(d[1]), "+f"(d[2]), "+f"(d[3])
        : "r"(a[0]), "r"(a[1]), "r"(a[2]), "r"(a[3]), "r"(b0), "r"(b1));
}

__device__ __forceinline__ void mm4(const float* A, const float* B, float* Cm) {
#pragma unroll
    for (int i = 0; i < 4; i++)
#pragma unroll
        for (int j = 0; j < 4; j++) {
            float s = 0.f;
#pragma unroll
            for (int kk = 0; kk < 4; kk++) s += A[i*4+kk] * B[kk*4+j];
            Cm[i*4+j] = s;
        }
}

// key permutation within 8-group: physical slot for logical key b:
//   b<4 -> 2b ; b>=4 -> 2(b-4)+1. Makes GEMM1 D-layout == GEMM2 A-layout.
__device__ __forceinline__ int kperm(int row) {
    int b = row & 7;
    int pb = (b < 4) ? (b << 1) : (((b - 4) << 1) | 1);
    return (row & ~7) | pb;
}

// ---------------------------------------------------------------------------
__global__ void prep_kernel(const float* __restrict__ vm, const float* __restrict__ Ks) {
    int t = threadIdx.x;
    if (t < 32) {
        float L = log2f(100.0f);
#pragma unroll
        for (int i = 0; i < 8; i++) {
            float f = exp2f(-L * (float)i / 8.0f);
            float sv, cv; sincosf((float)t * f, &sv, &cv);
            g_cos[t][i] = cv; g_sin[t][i] = sv;
        }
    }
    if (t < 4) {
        int c = t;
        const float* V  = vm + c*16;
        const float* Kc = Ks + c*9;
        float a = Kc[0] * (1.0f/512.0f);
        float b = Kc[4] * (1.0f/512.0f);
        float u = Kc[2] * (1.0f/512.0f) - 0.5f;
        float w = Kc[5] * (1.0f/512.0f) - 0.5f;
        float K4[16] = {a,0,u,0, 0,b,w,0, 0,0,1,0, 0,0,0,1};
        float Vl[16];
#pragma unroll
        for (int i = 0; i < 16; i++) Vl[i] = V[i];
        float P[16];
        mm4(K4, Vl, P);
#pragma unroll
        for (int i = 0; i < 4; i++)
#pragma unroll
            for (int jj = 0; jj < 4; jj++) { g_P[c][i*4+jj] = P[i*4+jj]; g_PT[c][i*4+jj] = P[jj*4+i]; }
        float Sm[16];
#pragma unroll
        for (int i = 0; i < 3; i++)
#pragma unroll
            for (int jj = 0; jj < 3; jj++) Sm[i*4+jj] = Vl[jj*4+i];
#pragma unroll
        for (int i = 0; i < 3; i++)
            Sm[i*4+3] = -(Sm[i*4+0]*Vl[3] + Sm[i*4+1]*Vl[7] + Sm[i*4+2]*Vl[11]);
        Sm[12]=0.f; Sm[13]=0.f; Sm[14]=0.f; Sm[15]=1.f;
        float Ki[16] = {1.0f/a,0,-u/a,0, 0,1.0f/b,-w/b,0, 0,0,1,0, 0,0,0,1};
        float Pi[16];
        mm4(Sm, Ki, Pi);
#pragma unroll
        for (int i = 0; i < 16; i++) g_Pinv[c][i] = Pi[i];
    }
}

// ---------------------------------------------------------------------------
__device__ __forceinline__ void transform_row_fwd(
    const float* __restrict__ in, float* __restrict__ out,
    const float* M, int px, int py)
{
    float x[64];
    const float4* in4 = (const float4*)in;
#pragma unroll
    for (int i = 0; i < 16; i++) {
        float4 tv = in4[i];
        x[4*i+0]=tv.x; x[4*i+1]=tv.y; x[4*i+2]=tv.z; x[4*i+3]=tv.w;
    }
    float y[64];
#pragma unroll
    for (int g = 0; g < 8; g++)
#pragma unroll
        for (int i = 0; i < 4; i++)
            y[g*4+i] = M[i*4+0]*x[g*4+0] + M[i*4+1]*x[g*4+1]
                     + M[i*4+2]*x[g*4+2] + M[i*4+3]*x[g*4+3];
#pragma unroll
    for (int i = 0; i < 8; i++) {
        float c1 = g_cos[px][i], s1 = g_sin[px][i];
        y[32+i] =  c1*x[32+i] + s1*x[40+i];
        y[40+i] = -s1*x[32+i] + c1*x[40+i];
        float c2 = g_cos[py][i], s2 = g_sin[py][i];
        y[48+i] =  c2*x[48+i] + s2*x[56+i];
        y[56+i] = -s2*x[48+i] + c2*x[56+i];
    }
    float4* out4 = (float4*)out;
#pragma unroll
    for (int i = 0; i < 16; i++)
        out4[i] = make_float4(tf32r(y[4*i+0]), tf32r(y[4*i+1]), tf32r(y[4*i+2]), tf32r(y[4*i+3]));
}

__global__ void transform_kv_kernel(const float* __restrict__ k, const float* __restrict__ v) {
    int r = blockIdx.x * blockDim.x + threadIdx.x;
    if (r >= NROWS) return;
    int s = r / NH;
    int h = r - s * NH;
    int c  = s >> 10;
    int px = s & 31;
    int py = (s >> 5) & 31;
    float M[16];
#pragma unroll
    for (int i = 0; i < 16; i++) M[i] = g_Pinv[c][i];
    size_t ibase = (size_t)r * HD;
    size_t obase = ((size_t)h * S_TOK + s) * HD;
    transform_row_fwd(k + ibase, g_k + obase, M, px, py);
    transform_row_fwd(v + ibase, g_v + obase, M, px, py);
}

// ---------------------------------------------------------------------------
// Flash attention via mma.sync.m16n8k8.tf32 + cp.async double buffering.
// Key-permuted K staging => GEMM1 D registers ARE GEMM2 A-fragments (no P
// SMEM round-trip).
// ---------------------------------------------------------------------------
__global__ void __launch_bounds__(QTILE)
attn_kernel(const float* __restrict__ q, float* __restrict__ out) {
    extern __shared__ char smraw[];
    const uint32_t sb = smem_u32(smraw);
    float* smf = (float*)smraw;
    float* QP  = (float*)(smraw + QP_OFF);

    const int tid  = threadIdx.x;
    const int w    = tid >> 5, lane = tid & 31;
    const int g    = lane >> 2, j = lane & 3;
    const int h    = blockIdx.y;
    const int s    = blockIdx.x * QTILE + tid;
    const int cam  = s >> 10, px = s & 31, py = (s >> 5) & 31;

    const float* kg = g_k + (size_t)h * S_TOK * HD;
    const float* vg = g_v + (size_t)h * S_TOK * HD;

    // ---- prefetch tile 0 (K rows permuted) ----
    {
#pragma unroll
        for (int i = 0; i < 4; i++) {
            int idx = tid + i*128;
            int row = idx >> 4, ch = idx & 15;
            cp16(sb + K_OFF + (uint32_t)(kperm(row)*KSTR + ch*4)*4, kg + idx*4);
            cp16(sb + V_OFF + (uint32_t)(row*VSTR + ch*4)*4, vg + idx*4);
        }
        CP_COMMIT();
    }

    // ---- Q transform (PT proj + fwd RoPE), fold scale*log2e, -> SMEM ----
    {
        float x[64];
        const float4* qr = (const float4*)(q + (size_t)s * (NH*HD) + (size_t)h * HD);
#pragma unroll
        for (int i = 0; i < 16; i++) {
            float4 tv = qr[i];
            x[4*i+0]=tv.x; x[4*i+1]=tv.y; x[4*i+2]=tv.z; x[4*i+3]=tv.w;
        }
        float y[64];
        const float* M = g_PT[cam];
#pragma unroll
        for (int gg = 0; gg < 8; gg++)
#pragma unroll
            for (int i = 0; i < 4; i++)
                y[gg*4+i] = M[i*4+0]*x[gg*4+0] + M[i*4+1]*x[gg*4+1]
                          + M[i*4+2]*x[gg*4+2] + M[i*4+3]*x[gg*4+3];
#pragma unroll
        for (int i = 0; i < 8; i++) {
            float c1 = g_cos[px][i], s1 = g_sin[px][i];
            y[32+i] =  c1*x[32+i] + s1*x[40+i];
            y[40+i] = -s1*x[32+i] + c1*x[40+i];
            float c2 = g_cos[py][i], s2 = g_sin[py][i];
            y[48+i] =  c2*x[48+i] + s2*x[56+i];
            y[56+i] = -s2*x[48+i] + c2*x[56+i];
        }
        const float SC = 0.18033688011112042f;  // (1/8)*log2(e)
        float4* dst = (float4*)&QP[(size_t)tid*QSTR];
#pragma unroll
        for (int i = 0; i < 16; i++)
            dst[i] = make_float4(tf32r(y[4*i+0]*SC), tf32r(y[4*i+1]*SC),
                                 tf32r(y[4*i+2]*SC), tf32r(y[4*i+3]*SC));
    }
    __syncthreads();

    // ---- Q A-fragments ----
    uint32_t qa[2][8][4];
#pragma unroll
    for (int m = 0; m < 2; m++)
#pragma unroll
        for (int t = 0; t < 8; t++) {
            int r0 = w*32 + m*16 + g, r1 = r0 + 8;
            qa[m][t][0] = __float_as_uint(QP[r0*QSTR + t*8+j]);
            qa[m][t][1] = __float_as_uint(QP[r1*QSTR + t*8+j]);
            qa[m][t][2] = __float_as_uint(QP[r0*QSTR + t*8+4+j]);
            qa[m][t][3] = __float_as_uint(QP[r1*QSTR + t*8+4+j]);
        }

    float o[2][8][4];
#pragma unroll
    for (int m = 0; m < 2; m++)
#pragma unroll
        for (int nb = 0; nb < 8; nb++)
#pragma unroll
            for (int e = 0; e < 4; e++) o[m][nb][e] = 0.f;
    float mrow[4] = {-1e30f, -1e30f, -1e30f, -1e30f};
    float lsum[4] = {0.f, 0.f, 0.f, 0.f};

#pragma unroll 1
    for (int t = 0; t < NTILES; t++) {
        CP_WAIT0();
        __syncthreads();

        const float* Kf = smf + (K_OFF/4) + (t & 1) * (32*KSTR);
        const float* Vf = smf + (V_OFF/4) + (t & 1) * (32*VSTR);

        // ---- prefetch next tile (K rows permuted) ----
        if (t + 1 < NTILES) {
            const float* ksrc = kg + (size_t)(t+1) * KTILE * HD;
            const float* vsrc = vg + (size_t)(t+1) * KTILE * HD;
            uint32_t kb = sb + K_OFF + (uint32_t)((t+1) & 1) * K_BUF_B;
            uint32_t vb = sb + V_OFF + (uint32_t)((t+1) & 1) * V_BUF_B;
#pragma unroll
            for (int i = 0; i < 4; i++) {
                int idx = tid + i*128;
                int row = idx >> 4, ch = idx & 15;
                cp16(kb + (uint32_t)(kperm(row)*KSTR + ch*4)*4, ksrc + idx*4);
                cp16(vb + (uint32_t)(row*VSTR + ch*4)*4, vsrc + idx*4);
            }
            CP_COMMIT();
        }

        // ---- GEMM1: S(128x32) = Q @ K^T (keys pre-permuted in SMEM) ----
        float sc[2][4][4];
#pragma unroll
        for (int m = 0; m < 2; m++)
#pragma unroll
            for (int nb = 0; nb < 4; nb++)
#pragma unroll
                for (int e = 0; e < 4; e++) sc[m][nb][e] = 0.f;
#pragma unroll
        for (int nb = 0; nb < 4; nb++)
#pragma unroll
            for (int tt = 0; tt < 8; tt++) {
                const float* kr = Kf + (nb*8 + g)*KSTR + tt*8 + j;
                float b0 = kr[0], b1 = kr[4];
                mma_tf32(sc[0][nb], qa[0][tt], b0, b1);
                mma_tf32(sc[1][nb], qa[1][tt], b0, b1);
            }

        // ---- online softmax (log2 domain; order-invariant over permuted keys) ----
        float rs[4];
#pragma unroll
        for (int m = 0; m < 2; m++)
#pragma unroll
            for (int hi = 0; hi < 2; hi++) {
                int rc = m*2 + hi;
                float mt = -1e30f;
#pragma unroll
                for (int nb = 0; nb < 4; nb++) {
                    mt = fmaxf(mt, sc[m][nb][hi*2]);
                    mt = fmaxf(mt, sc[m][nb][hi*2+1]);
                }
                mt = fmaxf(mt, __shfl_xor_sync(0xffffffffu, mt, 1));
                mt = fmaxf(mt, __shfl_xor_sync(0xffffffffu, mt, 2));
                float mn = fmaxf(mrow[rc], mt);
                rs[rc] = ex2(mrow[rc] - mn);
                mrow[rc] = mn;
                float ps = 0.f;
#pragma unroll
                for (int nb = 0; nb < 4; nb++) {
                    float p0 = ex2(sc[m][nb][hi*2]   - mn);
                    float p1 = ex2(sc[m][nb][hi*2+1] - mn);
                    sc[m][nb][hi*2] = p0; sc[m][nb][hi*2+1] = p1;
                    ps += p0 + p1;
                }
                ps += __shfl_xor_sync(0xffffffffu, ps, 1);
                ps += __shfl_xor_sync(0xffffffffu, ps, 2);
                lsum[rc] = lsum[rc]*rs[rc] + ps;
            }

        // ---- round P to tf32 in registers (becomes GEMM2 A-fragment) ----
#pragma unroll
        for (int m = 0; m < 2; m++)
#pragma unroll
            for (int nb = 0; nb < 4; nb++)
#pragma unroll
                for (int e = 0; e < 4; e++) sc[m][nb][e] = tf32r(sc[m][nb][e]);

        // ---- rescale O (skipped when no row max moved) ----
        bool allone = (rs[0]==1.f) & (rs[1]==1.f) & (rs[2]==1.f) & (rs[3]==1.f);
        if (!__all_sync(0xffffffffu, allone)) {
#pragma unroll
            for (int m = 0; m < 2; m++)
#pragma unroll
                for (int nb = 0; nb < 8; nb++) {
                    o[m][nb][0] *= rs[m*2];   o[m][nb][1] *= rs[m*2];
                    o[m][nb][2] *= rs[m*2+1]; o[m][nb][3] *= rs[m*2+1];
                }
        }

        // ---- GEMM2: O += P @ V ; A-fragments straight from sc registers ----
#pragma unroll
        for (int tk = 0; tk < 4; tk++) {
            uint32_t pa0[4], pa1[4];
            pa0[0] = __float_as_uint(sc[0][tk][0]);
            pa0[1] = __float_as_uint(sc[0][tk][2]);
            pa0[2] = __float_as_uint(sc[0][tk][1]);
            pa0[3] = __float_as_uint(sc[0][tk][3]);
            pa1[0] = __float_as_uint(sc[1][tk][0]);
            pa1[1] = __float_as_uint(sc[1][tk][2]);
            pa1[2] = __float_as_uint(sc[1][tk][1]);
            pa1[3] = __float_as_uint(sc[1][tk][3]);
#pragma unroll
            for (int nb = 0; nb < 8; nb++) {
                const float* vr = Vf + (tk*8 + j)*VSTR + nb*8 + g;
                float b0 = vr[0], b1 = vr[4*VSTR];
                mma_tf32(o[0][nb], pa0, b0, b1);
                mma_tf32(o[1][nb], pa1, b0, b1);
            }
        }
    }

    // ---- normalize, exchange O through SMEM, epilogue ----
    __syncthreads();
    float inv[4];
#pragma unroll
    for (int rc = 0; rc < 4; rc++) inv[rc] = 1.0f / lsum[rc];
#pragma unroll
    for (int m = 0; m < 2; m++) {
        int r0 = w*32 + m*16 + g, r1 = r0 + 8;
#pragma unroll
        for (int nb = 0; nb < 8; nb++) {
            *(float2*)&QP[r0*QSTR + nb*8 + 2*j] =
                make_float2(o[m][nb][0]*inv[m*2],   o[m][nb][1]*inv[m*2]);
            *(float2*)&QP[r1*QSTR + nb*8 + 2*j] =
                make_float2(o[m][nb][2]*inv[m*2+1], o[m][nb][3]*inv[m*2+1]);
        }
    }
    __syncthreads();

    {
        float acc[64];
#pragma unroll
        for (int i = 0; i < 16; i++) {
            float4 tv = *(const float4*)&QP[(size_t)tid*QSTR + i*4];
            acc[4*i+0]=tv.x; acc[4*i+1]=tv.y; acc[4*i+2]=tv.z; acc[4*i+3]=tv.w;
        }
        float y[64];
        const float* M = g_P[cam];
#pragma unroll
        for (int gg = 0; gg < 8; gg++)
#pragma unroll
            for (int i = 0; i < 4; i++)
                y[gg*4+i] = M[i*4+0]*acc[gg*4+0] + M[i*4+1]*acc[gg*4+1]
                          + M[i*4+2]*acc[gg*4+2] + M[i*4+3]*acc[gg*4+3];
#pragma unroll
        for (int i = 0; i < 8; i++) {
            float c1 = g_cos[px][i], s1 = g_sin[px][i];
            y[32+i] = c1*acc[32+i] - s1*acc[40+i];
            y[40+i] = s1*acc[32+i] + c1*acc[40+i];
            float c2 = g_cos[py][i], s2 = g_sin[py][i];
            y[48+i] = c2*acc[48+i] - s2*acc[56+i];
            y[56+i] = s2*acc[48+i] + c2*acc[56+i];
        }
        float4* o4 = (float4*)(out + (size_t)s * (NH*HD) + (size_t)h * HD);
#pragma unroll
        for (int i = 0; i < 16; i++)
            o4[i] = make_float4(y[4*i+0], y[4*i+1], y[4*i+2], y[4*i+3]);
    }
}

// ---------------------------------------------------------------------------
extern "C" void kernel_launch(void* const* d_in, const int* in_sizes, int n_in,
                              void* d_out, int out_size) {
    const float* q  = (const float*)d_in[0];
    const float* k  = (const float*)d_in[1];
    const float* v  = (const float*)d_in[2];
    const float* vm = (const float*)d_in[3];
    const float* Ks = (const float*)d_in[4];
    float* out = (float*)d_out;

    cudaFuncSetAttribute(attn_kernel, cudaFuncAttributeMaxDynamicSharedMemorySize, SMEM_BYTES);

    prep_kernel<<<1, 32>>>(vm, Ks);
    transform_kv_kernel<<<(NROWS + 255) / 256, 256>>>(k, v);
    attn_kernel<<<dim3(S_TOK / QTILE, NH), QTILE, SMEM_BYTES>>>(q, out);
}